// round 15
// baseline (speedup 1.0000x reference)
#include <cuda_runtime.h>
#include <cuda_fp16.h>
#include <math.h>
#include <stdint.h>

#define BB 64
#define TT 512
#define HH 1024
#define GG 4096              // 4*H
#define KK 2048              // concat K = I + H
#define NBLK 288             // 3 layers x 96 blocks
#define LBLK 96
#define ASTR 36              // A row stride (floats)
#define WSTR2 20             // W row stride (uint32 = half2 units), 16 data + 4 pad
#define NSTAGE 4

// Scratch (device globals: allocation-free per harness rules)
__device__ uint32_t g_wpack[(size_t)3 * GG * (KK / 2)]; // half2-packed W, 48 MB
__device__ float    g_bias [3 * GG];                    // bih+bhh
__device__ float    g_hstate[3 * BB * HH];              // per-layer h state
__device__ float    g_seq  [2][(size_t)BB * TT * HH];   // inter-layer sequence buffers
__device__ float    g_part [3][3][BB * GG];             // [layer][ksplit][64][4096]

// Per-layer barrier state; each counter on its own 128B line.
// g_gen monotonic (replay-safe); g_cnt returns to 0 each pass; g_done reset by pack.
__device__ unsigned          g_cnt [3 * 32];
__device__ volatile unsigned g_gen [3 * 32];
__device__ volatile unsigned g_done[3 * 32];

__device__ __forceinline__ void layer_barrier(int layer, unsigned done_val, bool write_done)
{
    __syncthreads();
    if (threadIdx.x == 0) {
        const int o = layer * 32;
        unsigned gen = g_gen[o];
        __threadfence();                          // release block's writes
        unsigned prev = atomicAdd(&g_cnt[o], 1u);
        if (prev == (unsigned)(LBLK - 1)) {
            atomicExch(&g_cnt[o], 0u);
            __threadfence();
            if (write_done) g_done[o] = done_val; // layer progress for layer+1
            g_gen[o] = gen + 1;                   // release
        } else {
            while (g_gen[o] == gen) __nanosleep(32);
            __threadfence();                      // acquire
        }
    }
    __syncthreads();
}

// ---------------------------------------------------------------------------
// fp16 MMA / cp.async helpers
// ---------------------------------------------------------------------------
__device__ __forceinline__ uint32_t pack_h2(float lo, float hi)
{
    __half2 h = __floats2half2_rn(lo, hi);
    return *(uint32_t*)&h;
}

__device__ __forceinline__ void mma_f16(float* d,
    uint32_t a0, uint32_t a1, uint32_t a2, uint32_t a3,
    uint32_t b0, uint32_t b1)
{
    asm("mma.sync.aligned.m16n8k16.row.col.f32.f16.f16.f32 "
        "{%0,%1,%2,%3}, {%4,%5,%6,%7}, {%8,%9}, {%0,%1,%2,%3};"
        : "+f"(d[0]), "+f"(d[1]), "+f"(d[2]), "+f"(d[3])
        : "r"(a0), "r"(a1), "r"(a2), "r"(a3), "r"(b0), "r"(b1));
}

__device__ __forceinline__ void cp_async16_cg(uint32_t saddr, const void* g)
{
    asm volatile("cp.async.cg.shared.global [%0], [%1], 16;" :: "r"(saddr), "l"(g));
}
__device__ __forceinline__ void cp_commit() { asm volatile("cp.async.commit_group;"); }
template<int N>
__device__ __forceinline__ void cp_wait() { asm volatile("cp.async.wait_group %0;" :: "n"(N)); }

// ---------------------------------------------------------------------------
// Pack kernel: W_cat -> half2 (packed along k), bias sum, zero h-state,
// reset per-replay progress counters.
// ---------------------------------------------------------------------------
__global__ void __launch_bounds__(256) pack_kernel(
    const float* __restrict__ Wih,
    const float* __restrict__ Whh,
    const float* __restrict__ bih,
    const float* __restrict__ bhh)
{
    size_t idx = (size_t)blockIdx.x * 256 + threadIdx.x;
    size_t k4  = idx & 511;          // 0..511 (K/4 groups)
    size_t ln  = idx >> 9;           // l*4096 + n, 0..12287
    int k = (int)(k4 * 4);

    const float* src = (k < 1024)
        ? (Wih + ln * 1024 + k)
        : (Whh + ln * 1024 + (k - 1024));
    float4 v = *(const float4*)src;
    uint2 u;
    u.x = pack_h2(v.x, v.y);
    u.y = pack_h2(v.z, v.w);
    *(uint2*)(g_wpack + ln * (KK / 2) + k / 2) = u;

    if (idx < 3 * GG)       g_bias[idx]   = bih[idx] + bhh[idx];
    if (idx < 3 * BB * HH)  g_hstate[idx] = 0.f;
    if (idx < 3)            g_done[idx * 32] = 0u;
}

// ---------------------------------------------------------------------------
// Persistent 3-layer LSTM kernel, per-layer barriers + cross-layer done poll.
// Block = (layer, ntile 0..31 of 128 cols, ksplit 0..2 of K=2048).
// fp16 MMA fp32-accumulate; 4-stage cp.async ring, one __syncthreads/chunk.
// ---------------------------------------------------------------------------
__global__ void __launch_bounds__(256, 2) lstm_pipeline_kernel(
    const float* __restrict__ x, float* __restrict__ out)
{
    extern __shared__ float smf[];
    float* Wb = smf;                                  // [4][128*20] uint32 data
    float* Ab = smf + NSTAGE * 128 * WSTR2;           // [4][64*36] fp32

    const int tid   = threadIdx.x;
    const int bid   = blockIdx.x;
    const int layer = bid / LBLK;
    const int rel   = bid % LBLK;
    const int ntile = rel & 31;
    const int ksl   = rel >> 5;
    const int n0    = ntile * 128;
    const int kbeg  = (ksl == 0) ? 0   : (ksl == 1) ? 672  : 1376;
    const int kend  = (ksl == 0) ? 672 : (ksl == 1) ? 1376 : 2048;
    const int nch   = (kend - kbeg) >> 5;             // 21 / 22 / 21 chunks of 32

    const int lane = tid & 31, wid = tid >> 5;
    const int g = lane >> 2, tg = lane & 3;

    // staging maps
    const int wr = tid >> 1, wh = tid & 1;            // W: 128 rows x 2 halves (8 uint32)
    const int ar = tid >> 2, aq = tid & 3;            // A: 64 rows x 4 quarters of 8 floats

    const uint32_t sW = (uint32_t)__cvta_generic_to_shared(
        (uint32_t*)Wb + wr * WSTR2 + wh * 8);
    const uint32_t sA = (uint32_t)__cvta_generic_to_shared(Ab + ar * ASTR + aq * 8);
    const uint32_t wBufB = 128 * WSTR2 * 4;
    const uint32_t aBufB = 64 * ASTR * 4;

    const uint32_t* Wsrc = g_wpack + (size_t)(layer * GG + n0 + wr) * (KK / 2) + wh * 8;
    const float*  inbase = (layer == 0) ? x : g_seq[layer - 1];
    const float*  hbase  = g_hstate + layer * (BB * HH);
    float* Pout = &g_part[layer][ksl][0];
    const float* bias = g_bias + layer * GG;
    float* seqout = (layer == 2) ? out : g_seq[layer];

    const int gt = rel * 256 + tid;                   // 0..24575
    float creg[3] = {0.f, 0.f, 0.f};

    for (int t = 0; t < TT; t++) {
        // cross-layer dependency: need seq[layer-1] for timestep t complete
        if (layer > 0) {
            if (tid == 0) {
                while (g_done[(layer - 1) * 32] < (unsigned)(t + 1)) __nanosleep(64);
                __threadfence();                      // acquire producer's writes
            }
            __syncthreads();
        }

        // ------------- phase A: fp16 MMA over this block's k-range -------------
        float acc[4][2][4];
        #pragma unroll
        for (int mt = 0; mt < 4; mt++)
            #pragma unroll
            for (int nt = 0; nt < 2; nt++)
                #pragma unroll
                for (int e = 0; e < 4; e++) acc[mt][nt][e] = 0.f;

        // prologue: stage chunks 0..2 into bufs 0..2, one group each
        #pragma unroll
        for (int j = 0; j < 3; j++) {
            int kb = kbeg + j * 32;
            uint32_t dW = sW + j * wBufB;
            const uint32_t* ws = Wsrc + (kb >> 1);
            cp_async16_cg(dW + 0,  ws + 0);
            cp_async16_cg(dW + 16, ws + 4);
            const float* as = (kb < 1024)
                ? inbase + ((size_t)ar * TT + t) * HH + kb + aq * 8
                : hbase + (size_t)ar * HH + (kb - 1024) + aq * 8;
            uint32_t dA = sA + j * aBufB;
            cp_async16_cg(dA + 0,  as + 0);
            cp_async16_cg(dA + 16, as + 4);
            cp_commit();
        }

        for (int i = 0; i < nch; i++) {
            if (i < nch - 2)      cp_wait<2>();
            else if (i == nch-2)  cp_wait<1>();
            else                  cp_wait<0>();
            __syncthreads();      // chunk i staged; all done reading buf (i+3)&3

            if (i + 3 < nch) {    // prefetch chunk i+3 into buf (i+3)&3
                int kb = kbeg + (i + 3) * 32;
                int pb = (i + 3) & 3;
                uint32_t dW = sW + pb * wBufB;
                const uint32_t* ws = Wsrc + (kb >> 1);
                cp_async16_cg(dW + 0,  ws + 0);
                cp_async16_cg(dW + 16, ws + 4);
                const float* as = (kb < 1024)
                    ? inbase + ((size_t)ar * TT + t) * HH + kb + aq * 8
                    : hbase + (size_t)ar * HH + (kb - 1024) + aq * 8;
                uint32_t dA = sA + pb * aBufB;
                cp_async16_cg(dA + 0,  as + 0);
                cp_async16_cg(dA + 16, as + 4);
                cp_commit();
            }

            const int buf = i & 3;
            const uint32_t* Wc = (const uint32_t*)Wb + buf * 128 * WSTR2;
            const float*    Ac = Ab + buf * 64 * ASTR;
            #pragma unroll
            for (int kk = 0; kk < 32; kk += 16) {        // two k16 steps
                const int kk2 = kk >> 1;                 // uint32 offset in W row
                uint32_t a[4][4];
                #pragma unroll
                for (int mt = 0; mt < 4; mt++) {
                    int r = mt * 16 + g;
                    float2 p0 = *(const float2*)(Ac + r * ASTR + kk + 2 * tg);
                    float2 p1 = *(const float2*)(Ac + (r + 8) * ASTR + kk + 2 * tg);
                    float2 p2 = *(const float2*)(Ac + r * ASTR + kk + 2 * tg + 8);
                    float2 p3 = *(const float2*)(Ac + (r + 8) * ASTR + kk + 2 * tg + 8);
                    a[mt][0] = pack_h2(p0.x, p0.y);
                    a[mt][1] = pack_h2(p1.x, p1.y);
                    a[mt][2] = pack_h2(p2.x, p2.y);
                    a[mt][3] = pack_h2(p3.x, p3.y);
                }
                uint32_t bf[2][2];
                #pragma unroll
                for (int nt = 0; nt < 2; nt++) {
                    int c = wid * 16 + nt * 8 + g;
                    bf[nt][0] = Wc[c * WSTR2 + kk2 + tg];
                    bf[nt][1] = Wc[c * WSTR2 + kk2 + tg + 4];
                }
                #pragma unroll
                for (int mt = 0; mt < 4; mt++)
                    #pragma unroll
                    for (int nt = 0; nt < 2; nt++)
                        mma_f16(acc[mt][nt], a[mt][0], a[mt][1], a[mt][2], a[mt][3],
                                bf[nt][0], bf[nt][1]);
            }
        }

        // write partials [64][128] -> g_part[layer][ksl]
        #pragma unroll
        for (int mt = 0; mt < 4; mt++) {
            int r = mt * 16 + g;
            #pragma unroll
            for (int nt = 0; nt < 2; nt++) {
                int c = n0 + wid * 16 + nt * 8 + tg * 2;
                *(float2*)(Pout + (size_t)r * GG + c) =
                    make_float2(acc[mt][nt][0], acc[mt][nt][1]);
                *(float2*)(Pout + (size_t)(r + 8) * GG + c) =
                    make_float2(acc[mt][nt][2], acc[mt][nt][3]);
            }
        }

        layer_barrier(layer, 0u, false);   // partials visible within layer

        // ------------- phase B: elementwise LSTM update -------------
        #pragma unroll
        for (int i = 0; i < 3; i++) {
            int e = gt + i * (LBLK * 256);
            if (e < BB * HH) {
                int b = e >> 10, j = e & 1023;
                float gi = bias[j];
                float gf = bias[j + 1024];
                float gg = bias[j + 2048];
                float go = bias[j + 3072];
                #pragma unroll
                for (int sp = 0; sp < 3; sp++) {
                    const float* P = &g_part[layer][sp][0] + (size_t)b * GG;
                    gi += P[j];
                    gf += P[j + 1024];
                    gg += P[j + 2048];
                    go += P[j + 3072];
                }
                float i_g = 1.f / (1.f + expf(-gi));
                float f_g = 1.f / (1.f + expf(-gf));
                float g_g = tanhf(gg);
                float o_g = 1.f / (1.f + expf(-go));
                float c = f_g * creg[i] + i_g * g_g;
                creg[i] = c;
                float h = o_g * tanhf(c);
                g_hstate[layer * BB * HH + e] = h;
                seqout[((size_t)b * TT + t) * HH + j] = h;
            }
        }

        layer_barrier(layer, (unsigned)(t + 1), true);   // h + seq visible; publish progress
    }
}

// ---------------------------------------------------------------------------
extern "C" void kernel_launch(void* const* d_in, const int* in_sizes, int n_in,
                              void* d_out, int out_size)
{
    const float* x   = (const float*)d_in[0];   // [B, T, I]
    const float* Wih = (const float*)d_in[1];   // [L, 4H, I]
    const float* Whh = (const float*)d_in[2];   // [L, 4H, H]
    const float* bih = (const float*)d_in[3];   // [L, 4H]
    const float* bhh = (const float*)d_in[4];   // [L, 4H]
    float* out = (float*)d_out;                 // [B, T, H]

    const int smem = NSTAGE * (128 * WSTR2 + 64 * ASTR) * 4;  // 77824 B
    cudaFuncSetAttribute(lstm_pipeline_kernel,
                         cudaFuncAttributeMaxDynamicSharedMemorySize, smem);

    pack_kernel<<<3 * GG * (KK / 4) / 256, 256>>>(Wih, Whh, bih, bhh);
    lstm_pipeline_kernel<<<NBLK, 256, smem>>>(x, out);
}

// round 17
// speedup vs baseline: 1.9830x; 1.9830x over previous
#include <cuda_runtime.h>
#include <cuda_fp16.h>
#include <math.h>
#include <stdint.h>

#define BB 64
#define TT 512
#define HH 1024
#define GG 4096              // 4*H
#define KK 2048              // concat K = I + H
#define NBLK 288             // 3 layers x 96 blocks
#define LBLK 96
#define NSTEP (TT + 2)       // 514 pipeline steps
#define STR 72               // smem row stride in halfs (conflict-free for LDSM)
#define KC 64
#define NSTAGE 3

// Scratch (device globals: allocation-free per harness rules)
__device__ uint32_t g_wpack[(size_t)3 * GG * (KK / 2)]; // half2-packed W, 48 MB
__device__ float    g_bias [3 * GG];                    // bih+bhh
__device__ __half   g_hstate[3 * BB * HH];              // per-layer h state (fp16)
__device__ __half   g_xh   [(size_t)BB * TT * HH];      // x pre-converted to fp16
__device__ __half   g_seqh [2][(size_t)BB * TT * HH];   // inter-layer seq (fp16)
__device__ float    g_part [3][3][BB * GG];             // [layer][ksplit][64][4096]

// Flat grid barrier (monotonic, zero-initialized) — proven R6/R10/R13/R14
__device__ unsigned g_bar_count;
__device__ volatile unsigned g_bar_gen;

__device__ __forceinline__ void grid_barrier()
{
    __syncthreads();
    if (threadIdx.x == 0) {
        unsigned gen = g_bar_gen;
        __threadfence();
        unsigned prev = atomicAdd(&g_bar_count, 1u);
        if (prev == (unsigned)(NBLK - 1)) {
            atomicExch(&g_bar_count, 0u);
            __threadfence();
            g_bar_gen = gen + 1;
        } else {
            while (g_bar_gen == gen) { }
            __threadfence();
        }
    }
    __syncthreads();
}

// ---------------------------------------------------------------------------
// helpers
// ---------------------------------------------------------------------------
__device__ __forceinline__ uint32_t pack_h2(float lo, float hi)
{
    __half2 h = __floats2half2_rn(lo, hi);
    return *(uint32_t*)&h;
}

__device__ __forceinline__ void mma_f16(float* d,
    uint32_t a0, uint32_t a1, uint32_t a2, uint32_t a3,
    uint32_t b0, uint32_t b1)
{
    asm("mma.sync.aligned.m16n8k16.row.col.f32.f16.f16.f32 "
        "{%0,%1,%2,%3}, {%4,%5,%6,%7}, {%8,%9}, {%0,%1,%2,%3};"
        : "+f"(d[0]), "+f"(d[1]), "+f"(d[2]), "+f"(d[3])
        : "r"(a0), "r"(a1), "r"(a2), "r"(a3), "r"(b0), "r"(b1));
}

__device__ __forceinline__ void ldsm_x4(uint32_t* r, uint32_t addr)
{
    asm volatile("ldmatrix.sync.aligned.m8n8.x4.shared.b16 {%0,%1,%2,%3}, [%4];"
        : "=r"(r[0]), "=r"(r[1]), "=r"(r[2]), "=r"(r[3]) : "r"(addr));
}

__device__ __forceinline__ void cp_async16_cg(uint32_t saddr, const void* g)
{
    asm volatile("cp.async.cg.shared.global [%0], [%1], 16;" :: "r"(saddr), "l"(g));
}
__device__ __forceinline__ void cp_commit() { asm volatile("cp.async.commit_group;"); }
template<int N>
__device__ __forceinline__ void cp_wait() { asm volatile("cp.async.wait_group %0;" :: "n"(N)); }

// ---------------------------------------------------------------------------
// Pack kernel: W_cat -> half2 (packed along k), bias sum, zero h-state.
// ---------------------------------------------------------------------------
__global__ void __launch_bounds__(256) pack_kernel(
    const float* __restrict__ Wih,
    const float* __restrict__ Whh,
    const float* __restrict__ bih,
    const float* __restrict__ bhh)
{
    size_t idx = (size_t)blockIdx.x * 256 + threadIdx.x;
    size_t k4  = idx & 511;          // 0..511 (K/4 groups)
    size_t ln  = idx >> 9;           // l*4096 + n, 0..12287
    int k = (int)(k4 * 4);

    const float* src = (k < 1024)
        ? (Wih + ln * 1024 + k)
        : (Whh + ln * 1024 + (k - 1024));
    float4 v = *(const float4*)src;
    uint2 u;
    u.x = pack_h2(v.x, v.y);
    u.y = pack_h2(v.z, v.w);
    *(uint2*)(g_wpack + ln * (KK / 2) + k / 2) = u;

    if (idx < 3 * GG)      g_bias[idx] = bih[idx] + bhh[idx];
    if (idx < 3 * BB * HH) g_hstate[idx] = __float2half_rn(0.f);
}

// x -> fp16 conversion (one-time per replay)
__global__ void __launch_bounds__(256) xconv_kernel(const float* __restrict__ x)
{
    size_t idx = (size_t)blockIdx.x * 256 + threadIdx.x;   // over BB*TT*HH/4
    float4 v = *(const float4*)(x + idx * 4);
    uint2 u;
    u.x = pack_h2(v.x, v.y);
    u.y = pack_h2(v.z, v.w);
    *(uint2*)((uint32_t*)g_xh + idx * 2) = u;
}

// ---------------------------------------------------------------------------
// Persistent 3-layer pipelined LSTM kernel (fp16 everything except accum).
// Block = (layer, ntile of 128 cols, ksplit of K=2048: 640/768/640).
// 3-stage cp.async ring, k-chunks of 64, ldmatrix fragments,
// 2(m)x4(n) warp tiling. Global barrier wavefront (R14-proven).
// ---------------------------------------------------------------------------
__global__ void __launch_bounds__(256, 2) lstm_pipeline_kernel(
    const float* __restrict__ x, float* __restrict__ out)
{
    extern __shared__ __half smh[];
    __half* Ws = smh;                        // [3][128*STR]
    __half* As = smh + NSTAGE * 128 * STR;   // [3][64*STR]

    const int tid   = threadIdx.x;
    const int bid   = blockIdx.x;
    const int layer = bid / LBLK;
    const int rel   = bid % LBLK;
    const int ntile = rel & 31;
    const int ksl   = rel >> 5;
    const int n0    = ntile * 128;
    const int kbeg  = (ksl == 0) ? 0   : (ksl == 1) ? 640  : 1408;
    const int kend  = (ksl == 0) ? 640 : (ksl == 1) ? 1408 : 2048;
    const int nch   = (kend - kbeg) >> 6;    // 10 / 12 / 10 chunks of 64

    const int lane = tid & 31, wid = tid >> 5;
    const int g = lane >> 2, tg = lane & 3;
    const int wm = wid >> 2;                 // 0..1 (32 rows each)
    const int wn = wid & 3;                  // 0..3 (32 cols each)

    // staging maps
    const int wr = tid >> 1, wh = tid & 1;   // W: 128 rows x 2 halves (4x16B each)
    const int ar = tid >> 2, aq = tid & 3;   // A: 64 rows x (segs aq, aq+4 of 8x16B)

    const uint32_t wBase = (uint32_t)__cvta_generic_to_shared(Ws);
    const uint32_t aBase = (uint32_t)__cvta_generic_to_shared(As);
    const uint32_t sW = wBase + (uint32_t)(wr * STR) * 2;
    const uint32_t sA = aBase + (uint32_t)(ar * STR) * 2;
    const uint32_t wBufB = 128 * STR * 2;    // 18432
    const uint32_t aBufB = 64 * STR * 2;     // 9216

    // ldmatrix per-lane offsets (bytes)
    const uint32_t aoff_b = (uint32_t)((lane & 15) * STR + (lane >> 4) * 8) * 2;
    const uint32_t woff_b = (uint32_t)(((lane & 7) + ((lane >> 4) << 3)) * STR
                                       + ((lane >> 3) & 1) * 8) * 2;

    const __half* Wsrc = (const __half*)g_wpack
        + (size_t)(layer * GG + n0 + wr) * KK;
    const __half* inb = (layer == 0) ? g_xh : g_seqh[layer - 1];
    const __half* hb  = g_hstate + layer * (BB * HH);
    float* Pout = &g_part[layer][ksl][0];
    const float* bias = g_bias + layer * GG;

    const int gt = rel * 256 + tid;          // 0..24575
    float creg[3] = {0.f, 0.f, 0.f};

    for (int s = 0; s < NSTEP; s++) {
        const int t = s - layer;
        const bool active = (t >= 0) && (t < TT);

        if (active) {
            float acc[2][4][4];
            #pragma unroll
            for (int mt = 0; mt < 2; mt++)
                #pragma unroll
                for (int nt = 0; nt < 4; nt++)
                    #pragma unroll
                    for (int e = 0; e < 4; e++) acc[mt][nt][e] = 0.f;

            // prologue: stage chunks 0,1 into stages 0,1
            #pragma unroll
            for (int j = 0; j < 2; j++) {
                int kb = kbeg + j * KC;
                uint32_t dW = sW + j * wBufB;
                const __half* ws = Wsrc + kb;
                #pragma unroll
                for (int q = 0; q < 4; q++) {
                    int seg = wh * 4 + q;
                    cp_async16_cg(dW + seg * 16, ws + seg * 8);
                }
                const __half* as = (kb < 1024)
                    ? inb + ((size_t)ar * TT + t) * HH + kb
                    : hb + (size_t)ar * HH + (kb - 1024);
                uint32_t dA = sA + j * aBufB;
                cp_async16_cg(dA + aq * 16,       as + aq * 8);
                cp_async16_cg(dA + (aq + 4) * 16, as + (aq + 4) * 8);
                cp_commit();
            }

            int buf = 0;
            for (int i = 0; i < nch; i++) {
                if (i < nch - 1) cp_wait<1>(); else cp_wait<0>();
                __syncthreads();             // chunk i staged; stage (i+2)%3 free

                if (i + 2 < nch) {           // prefetch chunk i+2
                    int kb = kbeg + (i + 2) * KC;
                    int pb = buf + 2; if (pb >= 3) pb -= 3;
                    uint32_t dW = sW + pb * wBufB;
                    const __half* ws = Wsrc + kb;
                    #pragma unroll
                    for (int q = 0; q < 4; q++) {
                        int seg = wh * 4 + q;
                        cp_async16_cg(dW + seg * 16, ws + seg * 8);
                    }
                    const __half* as = (kb < 1024)
                        ? inb + ((size_t)ar * TT + t) * HH + kb
                        : hb + (size_t)ar * HH + (kb - 1024);
                    uint32_t dA = sA + pb * aBufB;
                    cp_async16_cg(dA + aq * 16,       as + aq * 8);
                    cp_async16_cg(dA + (aq + 4) * 16, as + (aq + 4) * 8);
                    cp_commit();
                }

                const uint32_t aS = aBase + buf * aBufB;
                const uint32_t wS = wBase + buf * wBufB;
                #pragma unroll
                for (int kk = 0; kk < KC; kk += 16) {
                    uint32_t a[2][4];
                    #pragma unroll
                    for (int mt = 0; mt < 2; mt++)
                        ldsm_x4(a[mt],
                            aS + (uint32_t)((wm * 32 + mt * 16) * STR + kk) * 2 + aoff_b);
                    uint32_t b[4][2];
                    #pragma unroll
                    for (int np = 0; np < 2; np++) {
                        uint32_t r[4];
                        ldsm_x4(r,
                            wS + (uint32_t)((wn * 32 + np * 16) * STR + kk) * 2 + woff_b);
                        b[np * 2][0]     = r[0];
                        b[np * 2][1]     = r[1];
                        b[np * 2 + 1][0] = r[2];
                        b[np * 2 + 1][1] = r[3];
                    }
                    #pragma unroll
                    for (int mt = 0; mt < 2; mt++)
                        #pragma unroll
                        for (int nt = 0; nt < 4; nt++)
                            mma_f16(acc[mt][nt], a[mt][0], a[mt][1], a[mt][2], a[mt][3],
                                    b[nt][0], b[nt][1]);
                }
                buf = (buf + 1 == 3) ? 0 : buf + 1;
            }

            // write partials [64][128] -> g_part[layer][ksl]
            #pragma unroll
            for (int mt = 0; mt < 2; mt++) {
                int r = wm * 32 + mt * 16 + g;
                #pragma unroll
                for (int nt = 0; nt < 4; nt++) {
                    int c = n0 + wn * 32 + nt * 8 + tg * 2;
                    *(float2*)(Pout + (size_t)r * GG + c) =
                        make_float2(acc[mt][nt][0], acc[mt][nt][1]);
                    *(float2*)(Pout + (size_t)(r + 8) * GG + c) =
                        make_float2(acc[mt][nt][2], acc[mt][nt][3]);
                }
            }
        }

        grid_barrier();   // partials visible

        if (active) {
            #pragma unroll
            for (int i = 0; i < 3; i++) {
                int e = gt + i * (LBLK * 256);
                if (e < BB * HH) {
                    int b = e >> 10, j = e & 1023;
                    float gi = bias[j];
                    float gf = bias[j + 1024];
                    float gg = bias[j + 2048];
                    float go = bias[j + 3072];
                    #pragma unroll
                    for (int sp = 0; sp < 3; sp++) {
                        const float* P = &g_part[layer][sp][0] + (size_t)b * GG;
                        gi += P[j];
                        gf += P[j + 1024];
                        gg += P[j + 2048];
                        go += P[j + 3072];
                    }
                    float i_g = 1.f / (1.f + expf(-gi));
                    float f_g = 1.f / (1.f + expf(-gf));
                    float g_g = tanhf(gg);
                    float o_g = 1.f / (1.f + expf(-go));
                    float c = f_g * creg[i] + i_g * g_g;
                    creg[i] = c;
                    float h = o_g * tanhf(c);
                    __half hh = __float2half_rn(h);
                    g_hstate[layer * BB * HH + e] = hh;
                    if (layer < 2)
                        g_seqh[layer][((size_t)b * TT + t) * HH + j] = hh;
                    else
                        out[((size_t)b * TT + t) * HH + j] = h;
                }
            }
        }

        grid_barrier();   // h + seq visible before next step
    }
}

// ---------------------------------------------------------------------------
extern "C" void kernel_launch(void* const* d_in, const int* in_sizes, int n_in,
                              void* d_out, int out_size)
{
    const float* x   = (const float*)d_in[0];   // [B, T, I]
    const float* Wih = (const float*)d_in[1];   // [L, 4H, I]
    const float* Whh = (const float*)d_in[2];   // [L, 4H, H]
    const float* bih = (const float*)d_in[3];   // [L, 4H]
    const float* bhh = (const float*)d_in[4];   // [L, 4H]
    float* out = (float*)d_out;                 // [B, T, H]

    const int smem = NSTAGE * (128 * STR + 64 * STR) * 2;  // 82944 B
    cudaFuncSetAttribute(lstm_pipeline_kernel,
                         cudaFuncAttributeMaxDynamicSharedMemorySize, smem);

    pack_kernel<<<3 * GG * (KK / 4) / 256, 256>>>(Wih, Whh, bih, bhh);
    xconv_kernel<<<(BB * TT * HH / 4) / 256, 256>>>(x);
    lstm_pipeline_kernel<<<NBLK, 256, smem>>>(x, out);
}